// round 9
// baseline (speedup 1.0000x reference)
#include <cuda_runtime.h>
#include <cuda_fp16.h>
#include <cstdint>

#define BATCH 16
#define SEQ   256
#define DIM   512
#define G4    2048
#define LN_EPS 1e-5f

#define GROUPS 16                 // CTAs per batch
#define NCTA  (BATCH*GROUPS)     // 256
#define TPB   256
#define NWARP 8
#define KT    32                 // 16-wide k-tiles per row-block (512/16)
#define CKT   13                 // SMEM-cached k-tiles per layer per warp
#define PF    6                  // register-prefetched streamed tiles
#define WARP_CACHE_U4 (2*CKT*32)               // 832 uint4/warp
#define SMEM_W_BYTES (NWARP*WARP_CACHE_U4*16)  // 106496
#define OFF_H2  SMEM_W_BYTES                   // fp16 h buffer (1 KB)
#define OFF_RED (OFF_H2 + 1024)
#define OFF_C   (OFF_RED + NWARP*8)
#define SMEM_TOTAL (OFF_C + 16)               // ~107.6 KB -> 2 CTAs/SM

#define NFRAG ((size_t)BATCH*128*KT*32)        // uint4 fragment chunks (32 MB each)

// ---------------- static device scratch ----------------
__device__ uint4   d_w0f[NFRAG];              // whh0, A-fragment-major fp16
__device__ uint4   d_w1f[NFRAG];              // wih1+whh1, A-fragment-major fp16
__device__ float   d_pre0[(size_t)BATCH*SEQ*G4];
__device__ float   d_bias1[BATCH*G4];
__device__ float   d_gates[2*BATCH*G4];       // double-buffered by layer
__device__ float2  d_gstat[2*NCTA];
__device__ unsigned d_bar[BATCH*32];

// ---------------- helpers ----------------
__device__ __forceinline__ unsigned f2h2(float a, float b) {
    __half2 h = __floats2half2_rn(a, b);
    return *reinterpret_cast<unsigned*>(&h);
}
__device__ __forceinline__ unsigned long long pk2f(float x, float y) {
    unsigned long long r; asm("mov.b64 %0,{%1,%2};" : "=l"(r) : "f"(x), "f"(y)); return r;
}
__device__ __forceinline__ float2 upk2f(unsigned long long v) {
    float2 f; asm("mov.b64 {%0,%1},%2;" : "=f"(f.x), "=f"(f.y) : "l"(v)); return f;
}
__device__ __forceinline__ unsigned long long fma2(unsigned long long a,
                                                   unsigned long long b,
                                                   unsigned long long c) {
    unsigned long long d; asm("fma.rn.f32x2 %0,%1,%2,%3;" : "=l"(d) : "l"(a), "l"(b), "l"(c)); return d;
}
__device__ __forceinline__ float sigmoidf_(float x) {
    return __fdividef(1.f, 1.f + __expf(-x));
}
__device__ __forceinline__ float tanhf_(float x) {
    x = fminf(fmaxf(x, -12.f), 12.f);
    float t = __expf(2.f * x);
    return __fdividef(t - 1.f, t + 1.f);
}

// ---------------- prep: build A-fragment-major fp16 weights ----------------
__global__ void prep_kernel(const float* __restrict__ whh0,
                            const float* __restrict__ wih1,
                            const float* __restrict__ whh1,
                            const float* __restrict__ bih1,
                            const float* __restrict__ bhh1)
{
    size_t idx0 = (size_t)blockIdx.x * blockDim.x + threadIdx.x;
    size_t stride = (size_t)gridDim.x * blockDim.x;
    for (size_t i = idx0; i < NFRAG; i += stride) {
        unsigned lane = (unsigned)i & 31u;
        unsigned kt   = ((unsigned)(i >> 5)) & 31u;
        unsigned blk  = ((unsigned)(i >> 10)) & 127u;
        unsigned b    = (unsigned)(i >> 17);
        unsigned gid  = lane >> 2, tig = lane & 3;
        size_t s0 = ((size_t)b * G4 + blk * 16 + gid) * DIM + kt * 16 + tig * 4;
        size_t s1 = s0 + 8 * DIM;
        {
            float4 A0 = *(const float4*)(whh0 + s0);
            float4 A1 = *(const float4*)(whh0 + s1);
            uint4 o;
            o.x = f2h2(A0.x, A0.y); o.y = f2h2(A0.z, A0.w);
            o.z = f2h2(A1.x, A1.y); o.w = f2h2(A1.z, A1.w);
            d_w0f[i] = o;
        }
        {
            float4 U0 = *(const float4*)(wih1 + s0);
            float4 V0 = *(const float4*)(whh1 + s0);
            float4 U1 = *(const float4*)(wih1 + s1);
            float4 V1 = *(const float4*)(whh1 + s1);
            uint4 o;
            o.x = f2h2(U0.x + V0.x, U0.y + V0.y); o.y = f2h2(U0.z + V0.z, U0.w + V0.w);
            o.z = f2h2(U1.x + V1.x, U1.y + V1.y); o.w = f2h2(U1.z + V1.z, U1.w + V1.w);
            d_w1f[i] = o;
        }
    }
    if (idx0 < BATCH * G4) d_bias1[idx0] = bih1[idx0] + bhh1[idx0];
    if (idx0 < BATCH * 32) d_bar[idx0] = 0u;
}

// ---- SGEMM (f32x2): d_pre0[b][t][j] = wih0[b]@x[b,t] + bih0 + bhh0 ----
__global__ void __launch_bounds__(256) gemm_pre0(const float* __restrict__ x,
                                                 const float* __restrict__ wih0,
                                                 const float* __restrict__ bih0,
                                                 const float* __restrict__ bhh0)
{
    __shared__ float As[16][132];
    __shared__ float Bs[16][132];
    const int b  = blockIdx.y;
    const int mt = blockIdx.x & 15;
    const int nt = blockIdx.x >> 4;
    const float* A = wih0 + ((size_t)b * G4  + (size_t)mt * 128) * DIM;
    const float* B = x    + ((size_t)b * SEQ + (size_t)nt * 128) * DIM;
    const int tid = threadIdx.x;
    const int tr = tid & 15;
    const int tc = tid >> 4;

    unsigned long long acc2[8][4];
#pragma unroll
    for (int i = 0; i < 8; i++)
#pragma unroll
        for (int j = 0; j < 4; j++) acc2[i][j] = 0ull;

    for (int k0 = 0; k0 < DIM; k0 += 16) {
        __syncthreads();
#pragma unroll
        for (int p = 0; p < 2; p++) {
            int fid = tid + p * 256;
            int row = fid >> 2;
            int kq  = fid & 3;
            float4 va = *(const float4*)(A + (size_t)row * DIM + k0 + kq * 4);
            As[kq*4+0][row] = va.x; As[kq*4+1][row] = va.y;
            As[kq*4+2][row] = va.z; As[kq*4+3][row] = va.w;
            float4 vb = *(const float4*)(B + (size_t)row * DIM + k0 + kq * 4);
            Bs[kq*4+0][row] = vb.x; Bs[kq*4+1][row] = vb.y;
            Bs[kq*4+2][row] = vb.z; Bs[kq*4+3][row] = vb.w;
        }
        __syncthreads();
#pragma unroll
        for (int kk = 0; kk < 16; kk++) {
            float4 a0 = *(const float4*)&As[kk][tr*4];
            float4 a1 = *(const float4*)&As[kk][64 + tr*4];
            float4 b0 = *(const float4*)&Bs[kk][tc*4];
            float4 b1 = *(const float4*)&Bs[kk][64 + tc*4];
            float af[8] = {a0.x,a0.y,a0.z,a0.w,a1.x,a1.y,a1.z,a1.w};
            unsigned long long bp[4];
            bp[0] = pk2f(b0.x, b0.y); bp[1] = pk2f(b0.z, b0.w);
            bp[2] = pk2f(b1.x, b1.y); bp[3] = pk2f(b1.z, b1.w);
#pragma unroll
            for (int i = 0; i < 8; i++) {
                unsigned long long ap = pk2f(af[i], af[i]);
#pragma unroll
                for (int j = 0; j < 4; j++)
                    acc2[i][j] = fma2(ap, bp[j], acc2[i][j]);
            }
        }
    }

    float acc[8][8];
#pragma unroll
    for (int i = 0; i < 8; i++)
#pragma unroll
        for (int j = 0; j < 4; j++) {
            float2 f = upk2f(acc2[i][j]);
            acc[i][2*j] = f.x; acc[i][2*j+1] = f.y;
        }

    float biasv[8];
#pragma unroll
    for (int i = 0; i < 8; i++) {
        int j = mt * 128 + ((i < 4) ? (tr*4 + i) : (64 + tr*4 + (i - 4)));
        biasv[i] = bih0[b * G4 + j] + bhh0[b * G4 + j];
    }
#pragma unroll
    for (int jj = 0; jj < 8; jj++) {
        int t = nt * 128 + ((jj < 4) ? (tc*4 + jj) : (64 + tc*4 + (jj - 4)));
        float* dst = &d_pre0[((size_t)b * SEQ + t) * G4 + mt * 128];
        float4 v0, v1;
        v0.x = acc[0][jj] + biasv[0]; v0.y = acc[1][jj] + biasv[1];
        v0.z = acc[2][jj] + biasv[2]; v0.w = acc[3][jj] + biasv[3];
        v1.x = acc[4][jj] + biasv[4]; v1.y = acc[5][jj] + biasv[5];
        v1.z = acc[6][jj] + biasv[6]; v1.w = acc[7][jj] + biasv[7];
        *(float4*)(dst + tr * 4)      = v0;
        *(float4*)(dst + 64 + tr * 4) = v1;
    }
}

// ---------------- persistent LSTM kernel (2 CTAs/SM overlap) ----------------
__device__ __forceinline__ void group_barrier(unsigned* bar, unsigned* epoch, int tid) {
    __syncthreads();
    *epoch += GROUPS;
    unsigned target = *epoch;
    if (tid == 0) {
        asm volatile("red.release.gpu.global.add.u32 [%0],%1;"
                     :: "l"(bar), "r"(1u) : "memory");
        unsigned v;
        do {
            asm volatile("ld.acquire.gpu.global.u32 %0,[%1];"
                         : "=r"(v) : "l"(bar) : "memory");
        } while (v < target);
    }
    __syncthreads();
}

#define MMA16816(d, v, hb)                                                        \
    asm volatile("mma.sync.aligned.m16n8k16.row.col.f32.f16.f16.f32 "             \
                 "{%0,%1,%2,%3},{%4,%5,%6,%7},{%8,%9},{%0,%1,%2,%3};"             \
                 : "+f"(d[0]), "+f"(d[1]), "+f"(d[2]), "+f"(d[3])                 \
                 : "r"(v.x), "r"(v.z), "r"(v.y), "r"(v.w), "r"(hb.x), "r"(hb.y))

__global__ void __launch_bounds__(TPB, 2)
lstm_kernel(const float* __restrict__ lnw, const float* __restrict__ lnb,
            float* __restrict__ out)
{
    extern __shared__ __align__(16) unsigned char smem[];
    uint4*  s_w   = (uint4*)smem;
    __half* s_h2  = (__half*)(smem + OFF_H2);
    float2* s_red = (float2*)(smem + OFF_RED);
    float*  s_c   = (float*)(smem + OFF_C);

    const int cta = blockIdx.x;
    const int b   = cta >> 4;            // 16 CTAs per batch
    const int k   = cta & 15;
    const int tid = threadIdx.x;
    const int wid = tid >> 5;
    const int lane = tid & 31;
    const int gid = lane >> 2;
    const int tig = lane & 3;

    unsigned* bar = &d_bar[b * 32];
    unsigned epoch = 0;
    const int blk  = k * NWARP + wid;     // global 16-row block id within batch
    const int row0 = blk * 16;

    const uint4* Wg0 = d_w0f + ((size_t)b * 128 + blk) * (KT * 32);
    const uint4* Wg1 = d_w1f + ((size_t)b * 128 + blk) * (KT * 32);

    // ---- fill SMEM fragment cache: per warp, tiles 0..CKT-1 of each layer ----
    for (int i = tid; i < NWARP * WARP_CACHE_U4; i += TPB) {
        int w  = i / WARP_CACHE_U4;
        int r  = i % WARP_CACHE_U4;
        int l  = r / (CKT * 32);
        int rr = r % (CKT * 32);           // kt*32 + lane
        const uint4* src = (l ? d_w1f : d_w0f)
                         + ((size_t)b * 128 + k * NWARP + w) * (KT * 32) + rr;
        s_w[i] = *src;
    }

    // two dims per thread in pointwise
    const int d0 = tid, d1 = tid + TPB;
    const float gw00 = __ldg(lnw + d0),       gb00 = __ldg(lnb + d0);
    const float gw01 = __ldg(lnw + d1),       gb01 = __ldg(lnb + d1);
    const float gw10 = __ldg(lnw + DIM + d0), gb10 = __ldg(lnb + DIM + d0);
    const float gw11 = __ldg(lnw + DIM + d1), gb11 = __ldg(lnb + DIM + d1);

    float c0 = 0.f, c1 = 0.f;
    ((unsigned short*)s_h2)[d0] = 0;
    ((unsigned short*)s_h2)[d1] = 0;

    uint4 pf[PF];
#pragma unroll
    for (int j = 0; j < PF; j++) pf[j] = __ldcg(&Wg0[(CKT + j) * 32 + lane]);

    __syncthreads();

    for (int t = 0; t < SEQ; t++) {
#pragma unroll
        for (int l = 0; l < 2; l++) {
            const float* add = (l == 0) ? (d_pre0 + ((size_t)b * SEQ + t) * G4)
                                        : (d_bias1 + (size_t)b * G4);
            float* gates = d_gates + (size_t)l * BATCH * G4 + (size_t)b * G4;
            const uint4* Wg = l ? Wg1 : Wg0;
            const uint4* Ws = s_w + wid * WARP_CACHE_U4 + l * (CKT * 32);
            const char* hbp = (const char*)s_h2 + tig * 8;

            float da[4] = {0.f, 0.f, 0.f, 0.f};
            float db[4] = {0.f, 0.f, 0.f, 0.f};
#pragma unroll
            for (int kt = 0; kt < KT; kt++) {
                uint4 v = (kt < CKT) ? Ws[kt * 32 + lane]
                        : (kt < CKT + PF) ? pf[kt - CKT]
                                          : __ldcg(&Wg[kt * 32 + lane]);
                uint2 hb = *(const uint2*)(hbp + kt * 32);
                if (kt & 1) { MMA16816(db, v, hb); }
                else        { MMA16816(da, v, hb); }
            }
            float g0 = da[0] + db[0] + __ldg(add + row0 + gid);
            float g1 = da[2] + db[2] + __ldg(add + row0 + 8 + gid);
            if (tig == 0) {
                gates[row0 + gid]     = g0;
                gates[row0 + 8 + gid] = g1;
            }
            float s1 = g0 + g1;
            float s2 = fmaf(g0, g0, g1 * g1);
#pragma unroll
            for (int o = 16; o >= 4; o >>= 1) {
                s1 += __shfl_down_sync(0xffffffffu, s1, o);
                s2 += __shfl_down_sync(0xffffffffu, s2, o);
            }
            if (lane == 0) s_red[wid] = make_float2(s1, s2);
            __syncthreads();
            if (tid == 0) {
                float a = 0.f, c = 0.f;
#pragma unroll
                for (int i = 0; i < NWARP; i++) { a += s_red[i].x; c += s_red[i].y; }
                d_gstat[l * NCTA + cta] = make_float2(a, c);
            }
            group_barrier(bar, &epoch, tid);

            // ---- prefetch streamed tiles for the NEXT matvec ----
            {
                const uint4* Wn = l ? Wg0 : Wg1;
#pragma unroll
                for (int j = 0; j < PF; j++) pf[j] = __ldcg(&Wn[(CKT + j) * 32 + lane]);
            }

            // ---- pointwise (redundant per CTA; 2 dims per thread) ----
            {
                // gate q (512 rows) = CTAs 4q..4q+3 = float4 entries st4[2q], st4[2q+1]
                const float4* st4 = (const float4*)(&d_gstat[l * NCTA + b * GROUPS]);
                float m_[4], r_[4];
#pragma unroll
                for (int q = 0; q < 4; q++) {
                    float4 sv0 = __ldcg(st4 + q * 2);
                    float4 sv1 = __ldcg(st4 + q * 2 + 1);
                    float s  = (sv0.x + sv0.z) + (sv1.x + sv1.z);
                    float ss = (sv0.y + sv0.w) + (sv1.y + sv1.w);
                    float m = s * (1.f / 512.f);
                    float v = fmaf(-m, m, ss * (1.f / 512.f));
                    m_[q] = m;
                    r_[q] = rsqrtf(v + LN_EPS);
                }
                const float gw_0 = (l == 0) ? gw00 : gw10;
                const float gb_0 = (l == 0) ? gb00 : gb10;
                const float gw_1 = (l == 0) ? gw01 : gw11;
                const float gb_1 = (l == 0) ? gb01 : gb11;

                float xi0 = __ldcg(gates + d0),        xi1 = __ldcg(gates + d1);
                float xf0 = __ldcg(gates + 512 + d0),  xf1 = __ldcg(gates + 512 + d1);
                float xg0 = __ldcg(gates + 1024 + d0), xg1 = __ldcg(gates + 1024 + d1);
                float xo0 = __ldcg(gates + 1536 + d0), xo1 = __ldcg(gates + 1536 + d1);

                float iv0 = sigmoidf_(fmaf((xi0 - m_[0]) * r_[0], gw_0, gb_0));
                float fv0 = sigmoidf_(fmaf((xf0 - m_[1]) * r_[1], gw_0, gb_0));
                float gv0 = tanhf_(   fmaf((xg0 - m_[2]) * r_[2], gw_0, gb_0));
                float ov0 = sigmoidf_(fmaf((xo0 - m_[3]) * r_[3], gw_0, gb_0));
                float iv1 = sigmoidf_(fmaf((xi1 - m_[0]) * r_[0], gw_1, gb_1));
                float fv1 = sigmoidf_(fmaf((xf1 - m_[1]) * r_[1], gw_1, gb_1));
                float gv1 = tanhf_(   fmaf((xg1 - m_[2]) * r_[2], gw_1, gb_1));
                float ov1 = sigmoidf_(fmaf((xo1 - m_[3]) * r_[3], gw_1, gb_1));

                float cn0 = fmaf(fv0, c0, iv0 * gv0);
                float cn1 = fmaf(fv1, c1, iv1 * gv1);
                c0 = cn0; c1 = cn1;

                float a = cn0 + cn1, c2 = fmaf(cn0, cn0, cn1 * cn1);
#pragma unroll
                for (int o = 16; o > 0; o >>= 1) {
                    a  += __shfl_down_sync(0xffffffffu, a, o);
                    c2 += __shfl_down_sync(0xffffffffu, c2, o);
                }
                if (lane == 0) s_red[wid] = make_float2(a, c2);
                __syncthreads();
                if (tid == 0) {
                    float sa = 0.f, sb = 0.f;
#pragma unroll
                    for (int i = 0; i < NWARP; i++) { sa += s_red[i].x; sb += s_red[i].y; }
                    float m = sa * (1.f / 512.f);
                    float v = fmaf(-m, m, sb * (1.f / 512.f));
                    s_c[0] = m;
                    s_c[1] = rsqrtf(v + LN_EPS);
                }
                __syncthreads();
                float cm = s_c[0], cr = s_c[1];
                float hv0 = ov0 * tanhf_(fmaf((cn0 - cm) * cr, gw_0, gb_0));
                float hv1 = ov1 * tanhf_(fmaf((cn1 - cm) * cr, gw_1, gb_1));
                s_h2[d0] = __float2half_rn(hv0);
                s_h2[d1] = __float2half_rn(hv1);
                if (l == 1 && k == 0) {
                    float* o = out + ((size_t)b * SEQ + t) * DIM;
                    o[d0] = hv0;
                    o[d1] = hv1;
                }
                __syncthreads();   // s_h2 ready before next matvec
            }
        }
    }
}

extern "C" void kernel_launch(void* const* d_in, const int* in_sizes, int n_in,
                              void* d_out, int out_size) {
    const float* x    = (const float*)d_in[0];
    const float* wih0 = (const float*)d_in[1];
    const float* whh0 = (const float*)d_in[2];
    const float* bih0 = (const float*)d_in[3];
    const float* bhh0 = (const float*)d_in[4];
    const float* wih1 = (const float*)d_in[5];
    const float* whh1 = (const float*)d_in[6];
    const float* bih1 = (const float*)d_in[7];
    const float* bhh1 = (const float*)d_in[8];
    const float* ln_w = (const float*)d_in[9];
    const float* ln_b = (const float*)d_in[10];
    float* out = (float*)d_out;

    cudaFuncSetAttribute(lstm_kernel, cudaFuncAttributeMaxDynamicSharedMemorySize,
                         SMEM_TOTAL);

    prep_kernel<<<1024, 256>>>(whh0, wih1, whh1, bih1, bhh1);
    gemm_pre0<<<dim3(32, 16), 256>>>(x, wih0, bih0, bhh0);
    lstm_kernel<<<NCTA, TPB, SMEM_TOTAL>>>(ln_w, ln_b, out);
}

// round 10
// speedup vs baseline: 1.0024x; 1.0024x over previous
#include <cuda_runtime.h>
#include <cuda_fp16.h>
#include <cstdint>

#define BATCH 16
#define SEQ   256
#define DIM   512
#define G4    2048
#define LN_EPS 1e-5f

#define GROUPS 8                  // CTAs per batch
#define NCTA  (BATCH*GROUPS)     // 128
#define TPB   512
#define NWARP 16
#define KT    32                 // 16-wide k-tiles per row-block (512/16)
#define CKT   14                 // SMEM-cached k-tiles per layer per warp
#define PF    8                  // register-prefetched streamed tiles
#define WARP_CACHE_U4 (2*CKT*32)               // 896 uint4/warp
#define SMEM_W_BYTES (NWARP*WARP_CACHE_U4*16)  // 229376
#define OFF_H2  SMEM_W_BYTES                   // fp16 h buffer (1 KB)
#define OFF_RED (OFF_H2 + 1024)
#define OFF_C   (OFF_RED + NWARP*8)
#define SMEM_TOTAL (OFF_C + 16)               // ~225.2 KB -> 1 CTA/SM

#define NFRAG ((size_t)BATCH*128*KT*32)        // uint4 fragment chunks (32 MB each)

// ---------------- static device scratch ----------------
__device__ uint4   d_w0f[NFRAG];              // whh0, A-fragment-major fp16
__device__ uint4   d_w1f[NFRAG];              // wih1+whh1, A-fragment-major fp16
__device__ float   d_pre0[(size_t)BATCH*SEQ*G4];
__device__ float   d_bias1[BATCH*G4];
__device__ float   d_gates[2*BATCH*G4];       // double-buffered by layer
__device__ float2  d_gstat[2*NCTA];
__device__ unsigned d_bar[BATCH*32];

// ---------------- helpers ----------------
__device__ __forceinline__ unsigned f2h2(float a, float b) {
    __half2 h = __floats2half2_rn(a, b);
    return *reinterpret_cast<unsigned*>(&h);
}
__device__ __forceinline__ unsigned long long pk2f(float x, float y) {
    unsigned long long r; asm("mov.b64 %0,{%1,%2};" : "=l"(r) : "f"(x), "f"(y)); return r;
}
__device__ __forceinline__ float2 upk2f(unsigned long long v) {
    float2 f; asm("mov.b64 {%0,%1},%2;" : "=f"(f.x), "=f"(f.y) : "l"(v)); return f;
}
__device__ __forceinline__ unsigned long long fma2(unsigned long long a,
                                                   unsigned long long b,
                                                   unsigned long long c) {
    unsigned long long d; asm("fma.rn.f32x2 %0,%1,%2,%3;" : "=l"(d) : "l"(a), "l"(b), "l"(c)); return d;
}
__device__ __forceinline__ float sigmoidf_(float x) {
    return __fdividef(1.f, 1.f + __expf(-x));
}
__device__ __forceinline__ float tanhf_(float x) {
    x = fminf(fmaxf(x, -12.f), 12.f);
    float t = __expf(2.f * x);
    return __fdividef(t - 1.f, t + 1.f);
}

// ---------------- prep: build A-fragment-major fp16 weights ----------------
__global__ void prep_kernel(const float* __restrict__ whh0,
                            const float* __restrict__ wih1,
                            const float* __restrict__ whh1,
                            const float* __restrict__ bih1,
                            const float* __restrict__ bhh1)
{
    size_t idx0 = (size_t)blockIdx.x * blockDim.x + threadIdx.x;
    size_t stride = (size_t)gridDim.x * blockDim.x;
    for (size_t i = idx0; i < NFRAG; i += stride) {
        unsigned lane = (unsigned)i & 31u;
        unsigned kt   = ((unsigned)(i >> 5)) & 31u;
        unsigned blk  = ((unsigned)(i >> 10)) & 127u;
        unsigned b    = (unsigned)(i >> 17);
        unsigned gid  = lane >> 2, tig = lane & 3;
        size_t s0 = ((size_t)b * G4 + blk * 16 + gid) * DIM + kt * 16 + tig * 4;
        size_t s1 = s0 + 8 * DIM;
        {
            float4 A0 = *(const float4*)(whh0 + s0);
            float4 A1 = *(const float4*)(whh0 + s1);
            uint4 o;
            o.x = f2h2(A0.x, A0.y); o.y = f2h2(A0.z, A0.w);
            o.z = f2h2(A1.x, A1.y); o.w = f2h2(A1.z, A1.w);
            d_w0f[i] = o;
        }
        {
            float4 U0 = *(const float4*)(wih1 + s0);
            float4 V0 = *(const float4*)(whh1 + s0);
            float4 U1 = *(const float4*)(wih1 + s1);
            float4 V1 = *(const float4*)(whh1 + s1);
            uint4 o;
            o.x = f2h2(U0.x + V0.x, U0.y + V0.y); o.y = f2h2(U0.z + V0.z, U0.w + V0.w);
            o.z = f2h2(U1.x + V1.x, U1.y + V1.y); o.w = f2h2(U1.z + V1.z, U1.w + V1.w);
            d_w1f[i] = o;
        }
    }
    if (idx0 < BATCH * G4) d_bias1[idx0] = bih1[idx0] + bhh1[idx0];
    if (idx0 < BATCH * 32) d_bar[idx0] = 0u;
}

// ---- SGEMM (f32x2): d_pre0[b][t][j] = wih0[b]@x[b,t] + bih0 + bhh0 ----
__global__ void __launch_bounds__(256) gemm_pre0(const float* __restrict__ x,
                                                 const float* __restrict__ wih0,
                                                 const float* __restrict__ bih0,
                                                 const float* __restrict__ bhh0)
{
    __shared__ float As[16][132];
    __shared__ float Bs[16][132];
    const int b  = blockIdx.y;
    const int mt = blockIdx.x & 15;
    const int nt = blockIdx.x >> 4;
    const float* A = wih0 + ((size_t)b * G4  + (size_t)mt * 128) * DIM;
    const float* B = x    + ((size_t)b * SEQ + (size_t)nt * 128) * DIM;
    const int tid = threadIdx.x;
    const int tr = tid & 15;
    const int tc = tid >> 4;

    unsigned long long acc2[8][4];
#pragma unroll
    for (int i = 0; i < 8; i++)
#pragma unroll
        for (int j = 0; j < 4; j++) acc2[i][j] = 0ull;

    for (int k0 = 0; k0 < DIM; k0 += 16) {
        __syncthreads();
#pragma unroll
        for (int p = 0; p < 2; p++) {
            int fid = tid + p * 256;
            int row = fid >> 2;
            int kq  = fid & 3;
            float4 va = *(const float4*)(A + (size_t)row * DIM + k0 + kq * 4);
            As[kq*4+0][row] = va.x; As[kq*4+1][row] = va.y;
            As[kq*4+2][row] = va.z; As[kq*4+3][row] = va.w;
            float4 vb = *(const float4*)(B + (size_t)row * DIM + k0 + kq * 4);
            Bs[kq*4+0][row] = vb.x; Bs[kq*4+1][row] = vb.y;
            Bs[kq*4+2][row] = vb.z; Bs[kq*4+3][row] = vb.w;
        }
        __syncthreads();
#pragma unroll
        for (int kk = 0; kk < 16; kk++) {
            float4 a0 = *(const float4*)&As[kk][tr*4];
            float4 a1 = *(const float4*)&As[kk][64 + tr*4];
            float4 b0 = *(const float4*)&Bs[kk][tc*4];
            float4 b1 = *(const float4*)&Bs[kk][64 + tc*4];
            float af[8] = {a0.x,a0.y,a0.z,a0.w,a1.x,a1.y,a1.z,a1.w};
            unsigned long long bp[4];
            bp[0] = pk2f(b0.x, b0.y); bp[1] = pk2f(b0.z, b0.w);
            bp[2] = pk2f(b1.x, b1.y); bp[3] = pk2f(b1.z, b1.w);
#pragma unroll
            for (int i = 0; i < 8; i++) {
                unsigned long long ap = pk2f(af[i], af[i]);
#pragma unroll
                for (int j = 0; j < 4; j++)
                    acc2[i][j] = fma2(ap, bp[j], acc2[i][j]);
            }
        }
    }

    float acc[8][8];
#pragma unroll
    for (int i = 0; i < 8; i++)
#pragma unroll
        for (int j = 0; j < 4; j++) {
            float2 f = upk2f(acc2[i][j]);
            acc[i][2*j] = f.x; acc[i][2*j+1] = f.y;
        }

    float biasv[8];
#pragma unroll
    for (int i = 0; i < 8; i++) {
        int j = mt * 128 + ((i < 4) ? (tr*4 + i) : (64 + tr*4 + (i - 4)));
        biasv[i] = bih0[b * G4 + j] + bhh0[b * G4 + j];
    }
#pragma unroll
    for (int jj = 0; jj < 8; jj++) {
        int t = nt * 128 + ((jj < 4) ? (tc*4 + jj) : (64 + tc*4 + (jj - 4)));
        float* dst = &d_pre0[((size_t)b * SEQ + t) * G4 + mt * 128];
        float4 v0, v1;
        v0.x = acc[0][jj] + biasv[0]; v0.y = acc[1][jj] + biasv[1];
        v0.z = acc[2][jj] + biasv[2]; v0.w = acc[3][jj] + biasv[3];
        v1.x = acc[4][jj] + biasv[4]; v1.y = acc[5][jj] + biasv[5];
        v1.z = acc[6][jj] + biasv[6]; v1.w = acc[7][jj] + biasv[7];
        *(float4*)(dst + tr * 4)      = v0;
        *(float4*)(dst + 64 + tr * 4) = v1;
    }
}

// ---------------- persistent LSTM kernel (HMMA matvec, acq/rel barrier) ----------------
__device__ __forceinline__ void group_barrier(unsigned* bar, unsigned* epoch, int tid) {
    __syncthreads();
    *epoch += GROUPS;
    unsigned target = *epoch;
    if (tid == 0) {
        asm volatile("red.release.gpu.global.add.u32 [%0],%1;"
                     :: "l"(bar), "r"(1u) : "memory");
        unsigned v;
        do {
            asm volatile("ld.acquire.gpu.global.u32 %0,[%1];"
                         : "=r"(v) : "l"(bar) : "memory");
        } while (v < target);
    }
    __syncthreads();
}

#define MMA16816(d, v, hb)                                                        \
    asm volatile("mma.sync.aligned.m16n8k16.row.col.f32.f16.f16.f32 "             \
                 "{%0,%1,%2,%3},{%4,%5,%6,%7},{%8,%9},{%0,%1,%2,%3};"             \
                 : "+f"(d[0]), "+f"(d[1]), "+f"(d[2]), "+f"(d[3])                 \
                 : "r"(v.x), "r"(v.z), "r"(v.y), "r"(v.w), "r"(hb.x), "r"(hb.y))

__global__ void __launch_bounds__(TPB, 1)
lstm_kernel(const float* __restrict__ lnw, const float* __restrict__ lnb,
            float* __restrict__ out)
{
    extern __shared__ __align__(16) unsigned char smem[];
    uint4*  s_w   = (uint4*)smem;
    __half* s_h2  = (__half*)(smem + OFF_H2);
    float2* s_red = (float2*)(smem + OFF_RED);

    const int cta = blockIdx.x;
    const int b   = cta >> 3;
    const int k   = cta & 7;
    const int tid = threadIdx.x;
    const int wid = tid >> 5;
    const int lane = tid & 31;
    const int gid = lane >> 2;
    const int tig = lane & 3;

    unsigned* bar = &d_bar[b * 32];
    unsigned epoch = 0;
    const int blk  = k * NWARP + wid;     // global 16-row block id within batch
    const int row0 = blk * 16;

    const uint4* Wg0 = d_w0f + ((size_t)b * 128 + blk) * (KT * 32);
    const uint4* Wg1 = d_w1f + ((size_t)b * 128 + blk) * (KT * 32);

    // ---- fill SMEM fragment cache: per warp, tiles 0..CKT-1 of each layer ----
    for (int i = tid; i < NWARP * WARP_CACHE_U4; i += TPB) {
        int w  = i / WARP_CACHE_U4;
        int r  = i % WARP_CACHE_U4;
        int l  = r / (CKT * 32);
        int rr = r % (CKT * 32);           // kt*32 + lane
        const uint4* src = (l ? d_w1f : d_w0f)
                         + ((size_t)b * 128 + k * NWARP + w) * (KT * 32) + rr;
        s_w[i] = *src;
    }

    const float gw0 = __ldg(lnw + tid),       gb0 = __ldg(lnb + tid);
    const float gw1 = __ldg(lnw + DIM + tid), gb1 = __ldg(lnb + DIM + tid);

    float creg = 0.f;
    ((unsigned short*)s_h2)[tid] = 0;      // h = 0 (fp16)

    // initial prefetch for (t=0, l=0)
    uint4 pf[PF];
#pragma unroll
    for (int j = 0; j < PF; j++) pf[j] = __ldcg(&Wg0[(CKT + j) * 32 + lane]);

    __syncthreads();

    for (int t = 0; t < SEQ; t++) {
#pragma unroll
        for (int l = 0; l < 2; l++) {
            const float* add = (l == 0) ? (d_pre0 + ((size_t)b * SEQ + t) * G4)
                                        : (d_bias1 + (size_t)b * G4);
            float* gates = d_gates + (size_t)l * BATCH * G4 + (size_t)b * G4;
            const uint4* Wg = l ? Wg1 : Wg0;
            const uint4* Ws = s_w + wid * WARP_CACHE_U4 + l * (CKT * 32);
            const char* hbp = (const char*)s_h2 + tig * 8;

            float da[4] = {0.f, 0.f, 0.f, 0.f};
            float db[4] = {0.f, 0.f, 0.f, 0.f};
#pragma unroll
            for (int kt = 0; kt < KT; kt++) {
                uint4 v = (kt < CKT) ? Ws[kt * 32 + lane]
                        : (kt < CKT + PF) ? pf[kt - CKT]
                                          : __ldcg(&Wg[kt * 32 + lane]);
                uint2 hb = *(const uint2*)(hbp + kt * 32);
                if (kt & 1) { MMA16816(db, v, hb); }
                else        { MMA16816(da, v, hb); }
            }
            // every lane's D col is the gate (h replicated over columns)
            float g0 = da[0] + db[0] + __ldg(add + row0 + gid);
            float g1 = da[2] + db[2] + __ldg(add + row0 + 8 + gid);
            if (tig == 0) {
                gates[row0 + gid]     = g0;
                gates[row0 + 8 + gid] = g1;
            }

            // ---- prefetch streamed tiles for the NEXT matvec (independent of sync) ----
            {
                const uint4* Wn = l ? Wg0 : Wg1;   // next layer (wraps to l=0 next t)
#pragma unroll
                for (int j = 0; j < PF; j++) pf[j] = __ldcg(&Wn[(CKT + j) * 32 + lane]);
            }

            float s1 = g0 + g1;
            float s2 = fmaf(g0, g0, g1 * g1);
#pragma unroll
            for (int o = 16; o >= 4; o >>= 1) {      // sums lanes 0,4,...,28
                s1 += __shfl_down_sync(0xffffffffu, s1, o);
                s2 += __shfl_down_sync(0xffffffffu, s2, o);
            }
            if (lane == 0) s_red[wid] = make_float2(s1, s2);
            __syncthreads();
            if (wid == 0) {
                float2 v = (lane < NWARP) ? s_red[lane] : make_float2(0.f, 0.f);
                float a = v.x, c = v.y;
#pragma unroll
                for (int o = 16; o > 0; o >>= 1) {
                    a += __shfl_down_sync(0xffffffffu, a, o);
                    c += __shfl_down_sync(0xffffffffu, c, o);
                }
                if (lane == 0) d_gstat[l * NCTA + cta] = make_float2(a, c);
            }
            group_barrier(bar, &epoch, tid);

            // ---- pointwise (redundant per CTA) ----
            {
                const int d = tid;
                const float gw = (l == 0) ? gw0 : gw1;
                const float gb = (l == 0) ? gb0 : gb1;
                float xi = __ldcg(gates + d);
                float xf = __ldcg(gates + 512 + d);
                float xg = __ldcg(gates + 1024 + d);
                float xo = __ldcg(gates + 1536 + d);
                const float4* st4 = (const float4*)(&d_gstat[l * NCTA + b * 8]);
                float m_[4], r_[4];
#pragma unroll
                for (int q = 0; q < 4; q++) {
                    float4 sv = __ldcg(st4 + q);
                    float s  = sv.x + sv.z;
                    float ss = sv.y + sv.w;
                    float m  = s * (1.f / 512.f);
                    float v  = fmaf(-m, m, ss * (1.f / 512.f));
                    m_[q] = m;
                    r_[q] = rsqrtf(v + LN_EPS);
                }
                float iv = sigmoidf_(fmaf((xi - m_[0]) * r_[0], gw, gb));
                float fv = sigmoidf_(fmaf((xf - m_[1]) * r_[1], gw, gb));
                float gv = tanhf_(   fmaf((xg - m_[2]) * r_[2], gw, gb));
                float ov = sigmoidf_(fmaf((xo - m_[3]) * r_[3], gw, gb));
                float cn = fmaf(fv, creg, iv * gv);
                creg = cn;

                float a = cn, c2 = cn * cn;
#pragma unroll
                for (int o = 16; o > 0; o >>= 1) {
                    a  += __shfl_down_sync(0xffffffffu, a, o);
                    c2 += __shfl_down_sync(0xffffffffu, c2, o);
                }
                if (lane == 0) s_red[wid] = make_float2(a, c2);
                __syncthreads();
                // every thread reduces the 16 partials (broadcast LDS; no tid0 chain)
                float sa = 0.f, sb = 0.f;
#pragma unroll
                for (int i = 0; i < NWARP; i++) {
                    float2 v = s_red[i];
                    sa += v.x; sb += v.y;
                }
                float cm = sa * (1.f / 512.f);
                float cvv = fmaf(-cm, cm, sb * (1.f / 512.f));
                float cr = rsqrtf(cvv + LN_EPS);

                float hv = ov * tanhf_(fmaf((cn - cm) * cr, gw, gb));
                __syncthreads();   // all s_red reads done before next layer reuses it
                s_h2[d] = __float2half_rn(hv);
                if (l == 1 && k == 0)
                    out[((size_t)b * SEQ + t) * DIM + d] = hv;
                __syncthreads();   // s_h2 ready before next matvec
            }
        }
    }
}

extern "C" void kernel_launch(void* const* d_in, const int* in_sizes, int n_in,
                              void* d_out, int out_size) {
    const float* x    = (const float*)d_in[0];
    const float* wih0 = (const float*)d_in[1];
    const float* whh0 = (const float*)d_in[2];
    const float* bih0 = (const float*)d_in[3];
    const float* bhh0 = (const float*)d_in[4];
    const float* wih1 = (const float*)d_in[5];
    const float* whh1 = (const float*)d_in[6];
    const float* bih1 = (const float*)d_in[7];
    const float* bhh1 = (const float*)d_in[8];
    const float* ln_w = (const float*)d_in[9];
    const float* ln_b = (const float*)d_in[10];
    float* out = (float*)d_out;

    cudaFuncSetAttribute(lstm_kernel, cudaFuncAttributeMaxDynamicSharedMemorySize,
                         SMEM_TOTAL);

    prep_kernel<<<1024, 256>>>(whh0, wih1, whh1, bih1, bhh1);
    gemm_pre0<<<dim3(32, 16), 256>>>(x, wih0, bih0, bhh0);
    lstm_kernel<<<NCTA, TPB, SMEM_TOTAL>>>(ln_w, ln_b, out);
}

// round 11
// speedup vs baseline: 1.0752x; 1.0726x over previous
#include <cuda_runtime.h>
#include <cuda_fp16.h>
#include <cstdint>

#define BATCH 16
#define SEQ   256
#define DIM   512
#define G4    2048
#define LN_EPS 1e-5f

#define GROUPS 8                  // CTAs per batch
#define NCTA  (BATCH*GROUPS)     // 128
#define TPB   512
#define NWARP 16
#define KT    32                 // 16-wide k-tiles per row-block (512/16)
#define CKT   13                 // SMEM-cached k-tiles per layer per warp
#define PF    6                  // register-prefetched streamed tiles
#define WARP_CACHE_U4 (2*CKT*32)               // 832 uint4/warp
#define SMEM_W_BYTES (NWARP*WARP_CACHE_U4*16)  // 212992
#define OFF_H2  SMEM_W_BYTES                   // fp16 h buffer (1 KB)
#define OFF_RED (OFF_H2 + 1024)
#define OFF_C   (OFF_RED + NWARP*8)
#define SMEM_TOTAL (OFF_C + 16)

#define NFRAG ((size_t)BATCH*128*KT*32)        // uint4 fragment chunks (32 MB each)
#define NXF   ((size_t)BATCH*32*KT*32)         // x B-fragments (uint2): 4 MB

// ---------------- static device scratch ----------------
__device__ uint4   d_w0f[NFRAG];              // whh0, A-fragment-major fp16
__device__ uint4   d_w1f[NFRAG];              // wih1+whh1, A-fragment-major fp16
__device__ uint4   d_wxf[NFRAG];              // wih0, A-fragment-major fp16
__device__ uint2   d_xf [NXF];                // x, B-fragment-major fp16
__device__ float   d_pre0[(size_t)BATCH*SEQ*G4];
__device__ float   d_bias1[BATCH*G4];
__device__ float   d_gates[2*BATCH*G4];       // double-buffered by layer
__device__ float2  d_gstat[2*NCTA];
__device__ unsigned d_bar[BATCH*32];

// ---------------- helpers ----------------
__device__ __forceinline__ unsigned f2h2(float a, float b) {
    __half2 h = __floats2half2_rn(a, b);
    return *reinterpret_cast<unsigned*>(&h);
}
__device__ __forceinline__ float sigmoidf_(float x) {
    return __fdividef(1.f, 1.f + __expf(-x));
}
__device__ __forceinline__ float tanhf_(float x) {
    x = fminf(fmaxf(x, -12.f), 12.f);
    float t = __expf(2.f * x);
    return __fdividef(t - 1.f, t + 1.f);
}

#define MMA16816(d, v, hb)                                                        \
    asm volatile("mma.sync.aligned.m16n8k16.row.col.f32.f16.f16.f32 "             \
                 "{%0,%1,%2,%3},{%4,%5,%6,%7},{%8,%9},{%0,%1,%2,%3};"             \
                 : "+f"(d[0]), "+f"(d[1]), "+f"(d[2]), "+f"(d[3])                 \
                 : "r"(v.x), "r"(v.z), "r"(v.y), "r"(v.w), "r"(hb.x), "r"(hb.y))

// ---------------- prep: build A/B-fragment fp16 tensors ----------------
__global__ void prep_kernel(const float* __restrict__ x,
                            const float* __restrict__ wih0,
                            const float* __restrict__ whh0,
                            const float* __restrict__ wih1,
                            const float* __restrict__ whh1,
                            const float* __restrict__ bih1,
                            const float* __restrict__ bhh1)
{
    size_t idx0 = (size_t)blockIdx.x * blockDim.x + threadIdx.x;
    size_t stride = (size_t)gridDim.x * blockDim.x;
    for (size_t i = idx0; i < NFRAG; i += stride) {
        unsigned lane = (unsigned)i & 31u;
        unsigned kt   = ((unsigned)(i >> 5)) & 31u;
        unsigned blk  = ((unsigned)(i >> 10)) & 127u;
        unsigned b    = (unsigned)(i >> 17);
        unsigned gid  = lane >> 2, tig = lane & 3;
        size_t s0 = ((size_t)b * G4 + blk * 16 + gid) * DIM + kt * 16 + tig * 4;
        size_t s1 = s0 + 8 * DIM;
        {
            float4 A0 = *(const float4*)(whh0 + s0);
            float4 A1 = *(const float4*)(whh0 + s1);
            uint4 o;
            o.x = f2h2(A0.x, A0.y); o.y = f2h2(A0.z, A0.w);
            o.z = f2h2(A1.x, A1.y); o.w = f2h2(A1.z, A1.w);
            d_w0f[i] = o;
        }
        {
            float4 A0 = *(const float4*)(wih0 + s0);
            float4 A1 = *(const float4*)(wih0 + s1);
            uint4 o;
            o.x = f2h2(A0.x, A0.y); o.y = f2h2(A0.z, A0.w);
            o.z = f2h2(A1.x, A1.y); o.w = f2h2(A1.z, A1.w);
            d_wxf[i] = o;
        }
        {
            float4 U0 = *(const float4*)(wih1 + s0);
            float4 V0 = *(const float4*)(whh1 + s0);
            float4 U1 = *(const float4*)(wih1 + s1);
            float4 V1 = *(const float4*)(whh1 + s1);
            uint4 o;
            o.x = f2h2(U0.x + V0.x, U0.y + V0.y); o.y = f2h2(U0.z + V0.z, U0.w + V0.w);
            o.z = f2h2(U1.x + V1.x, U1.y + V1.y); o.w = f2h2(U1.z + V1.z, U1.w + V1.w);
            d_w1f[i] = o;
        }
    }
    // x B-fragments: d_xf[((b*32+tg)*KT+kt)*32+lane] = x[b][tg*8+gid][kt*16+tig*4 ..+3]
    for (size_t i = idx0; i < NXF; i += stride) {
        unsigned lane = (unsigned)i & 31u;
        unsigned kt   = ((unsigned)(i >> 5)) & 31u;
        unsigned tg   = ((unsigned)(i >> 10)) & 31u;
        unsigned b    = (unsigned)(i >> 15);
        unsigned gid  = lane >> 2, tig = lane & 3;
        float4 xv = *(const float4*)(x + ((size_t)(b * SEQ + tg * 8 + gid) * DIM
                                          + kt * 16 + tig * 4));
        d_xf[i] = make_uint2(f2h2(xv.x, xv.y), f2h2(xv.z, xv.w));
    }
    if (idx0 < BATCH * G4) d_bias1[idx0] = bih1[idx0] + bhh1[idx0];
    if (idx0 < BATCH * 32) d_bar[idx0] = 0u;
}

// ---- HMMA GEMM: d_pre0[b][t][j] = wih0[b]@x[b,t] + bih0 + bhh0 ----
// CTA = 4 row-blocks (64 rows) x all 256 t; 8 warps: warp w -> rowblk w/2, t-half w&1.
__global__ void __launch_bounds__(256) gemm_pre0_h(const float* __restrict__ bih0,
                                                   const float* __restrict__ bhh0)
{
    extern __shared__ __align__(16) unsigned char gsm[];
    uint4* s_a = (uint4*)gsm;                      // 4 * KT * 32 uint4 = 64 KB

    const int b  = blockIdx.y;
    const int rg = blockIdx.x;                     // 0..31 -> rowblocks rg*4..rg*4+3
    const int tid = threadIdx.x;
    const int wid = tid >> 5;
    const int lane = tid & 31;
    const int gid = lane >> 2;
    const int tig = lane & 3;

    const uint4* Asrc = d_wxf + ((size_t)b * 128 + rg * 4) * (KT * 32);
    for (int i = tid; i < 4 * KT * 32; i += 256) s_a[i] = Asrc[i];
    __syncthreads();

    const int rb = wid >> 1;
    const int row0g = (rg * 4 + rb) * 16;
    const uint4* As = s_a + rb * (KT * 32);
    const float bias0 = __ldg(bih0 + b * G4 + row0g + gid)
                      + __ldg(bhh0 + b * G4 + row0g + gid);
    const float bias1 = __ldg(bih0 + b * G4 + row0g + gid + 8)
                      + __ldg(bhh0 + b * G4 + row0g + gid + 8);

    const int tg0 = (wid & 1) * 16;
    for (int tg = tg0; tg < tg0 + 16; tg++) {
        const uint2* xf = d_xf + ((size_t)(b * 32 + tg) * KT) * 32;
        float d0[4] = {0.f, 0.f, 0.f, 0.f};
        float d1[4] = {0.f, 0.f, 0.f, 0.f};
#pragma unroll
        for (int kt = 0; kt < KT; kt++) {
            uint4 v  = As[kt * 32 + lane];
            uint2 hb = __ldg(&xf[kt * 32 + lane]);
            if (kt & 1) { MMA16816(d1, v, hb); }
            else        { MMA16816(d0, v, hb); }
        }
        const int t = tg * 8;
        float* base = d_pre0 + ((size_t)b * SEQ + t) * G4;
        base[(2 * tig)     * G4 + row0g + gid]     = d0[0] + d1[0] + bias0;
        base[(2 * tig + 1) * G4 + row0g + gid]     = d0[1] + d1[1] + bias0;
        base[(2 * tig)     * G4 + row0g + gid + 8] = d0[2] + d1[2] + bias1;
        base[(2 * tig + 1) * G4 + row0g + gid + 8] = d0[3] + d1[3] + bias1;
    }
}

// ---------------- persistent LSTM kernel (R6 verbatim) ----------------
__device__ __forceinline__ void group_barrier(unsigned* bar, unsigned* epoch, int tid) {
    __syncthreads();
    *epoch += GROUPS;
    unsigned target = *epoch;
    if (tid == 0) {
        asm volatile("red.release.gpu.global.add.u32 [%0],%1;"
                     :: "l"(bar), "r"(1u) : "memory");
        unsigned v;
        do {
            asm volatile("ld.acquire.gpu.global.u32 %0,[%1];"
                         : "=r"(v) : "l"(bar) : "memory");
        } while (v < target);
    }
    __syncthreads();
}

__global__ void __launch_bounds__(TPB, 1)
lstm_kernel(const float* __restrict__ lnw, const float* __restrict__ lnb,
            float* __restrict__ out)
{
    extern __shared__ __align__(16) unsigned char smem[];
    uint4*  s_w   = (uint4*)smem;
    __half* s_h2  = (__half*)(smem + OFF_H2);
    float2* s_red = (float2*)(smem + OFF_RED);
    float*  s_c   = (float*)(smem + OFF_C);

    const int cta = blockIdx.x;
    const int b   = cta >> 3;
    const int k   = cta & 7;
    const int tid = threadIdx.x;
    const int wid = tid >> 5;
    const int lane = tid & 31;
    const int gid = lane >> 2;
    const int tig = lane & 3;

    unsigned* bar = &d_bar[b * 32];
    unsigned epoch = 0;
    const int blk  = k * 16 + wid;        // global 16-row block id within batch
    const int row0 = blk * 16;

    const uint4* Wg0 = d_w0f + ((size_t)b * 128 + blk) * (KT * 32);
    const uint4* Wg1 = d_w1f + ((size_t)b * 128 + blk) * (KT * 32);

    // ---- fill SMEM fragment cache: per warp, tiles 0..CKT-1 of each layer ----
    for (int i = tid; i < NWARP * WARP_CACHE_U4; i += TPB) {
        int w  = i / WARP_CACHE_U4;
        int r  = i % WARP_CACHE_U4;
        int l  = r / (CKT * 32);
        int rr = r % (CKT * 32);           // kt*32 + lane
        const uint4* src = (l ? d_w1f : d_w0f)
                         + ((size_t)b * 128 + k * 16 + w) * (KT * 32) + rr;
        s_w[i] = *src;
    }

    const float gw0 = __ldg(lnw + tid),       gb0 = __ldg(lnb + tid);
    const float gw1 = __ldg(lnw + DIM + tid), gb1 = __ldg(lnb + DIM + tid);

    float creg = 0.f;
    ((unsigned short*)s_h2)[tid] = 0;      // h = 0 (fp16)

    // initial prefetch for (t=0, l=0)
    uint4 pf[PF];
#pragma unroll
    for (int j = 0; j < PF; j++) pf[j] = __ldcg(&Wg0[(CKT + j) * 32 + lane]);

    __syncthreads();

    for (int t = 0; t < SEQ; t++) {
#pragma unroll
        for (int l = 0; l < 2; l++) {
            const float* add = (l == 0) ? (d_pre0 + ((size_t)b * SEQ + t) * G4)
                                        : (d_bias1 + (size_t)b * G4);
            float* gates = d_gates + (size_t)l * BATCH * G4 + (size_t)b * G4;
            const uint4* Wg = l ? Wg1 : Wg0;
            const uint4* Ws = s_w + wid * WARP_CACHE_U4 + l * (CKT * 32);
            const char* hbp = (const char*)s_h2 + tig * 8;

            float da[4] = {0.f, 0.f, 0.f, 0.f};
            float db[4] = {0.f, 0.f, 0.f, 0.f};
#pragma unroll
            for (int kt = 0; kt < KT; kt++) {
                uint4 v = (kt < CKT) ? Ws[kt * 32 + lane]
                        : (kt < CKT + PF) ? pf[kt - CKT]
                                          : __ldcg(&Wg[kt * 32 + lane]);
                uint2 hb = *(const uint2*)(hbp + kt * 32);
                if (kt & 1) { MMA16816(db, v, hb); }
                else        { MMA16816(da, v, hb); }
            }
            // every lane's D col is the gate (h replicated over columns)
            float g0 = da[0] + db[0] + __ldg(add + row0 + gid);
            float g1 = da[2] + db[2] + __ldg(add + row0 + 8 + gid);
            if (tig == 0) {
                gates[row0 + gid]     = g0;
                gates[row0 + 8 + gid] = g1;
            }
            float s1 = g0 + g1;
            float s2 = fmaf(g0, g0, g1 * g1);
#pragma unroll
            for (int o = 16; o >= 4; o >>= 1) {      // sums lanes 0,4,...,28
                s1 += __shfl_down_sync(0xffffffffu, s1, o);
                s2 += __shfl_down_sync(0xffffffffu, s2, o);
            }
            if (lane == 0) s_red[wid] = make_float2(s1, s2);
            __syncthreads();
            if (tid == 0) {
                float a = 0.f, c = 0.f;
#pragma unroll
                for (int i = 0; i < NWARP; i++) { a += s_red[i].x; c += s_red[i].y; }
                d_gstat[l * NCTA + cta] = make_float2(a, c);
            }
            group_barrier(bar, &epoch, tid);

            // ---- prefetch streamed tiles for the NEXT matvec (weights are static) ----
            {
                const uint4* Wn = l ? Wg0 : Wg1;   // next layer (wraps to l=0 next t)
#pragma unroll
                for (int j = 0; j < PF; j++) pf[j] = __ldcg(&Wn[(CKT + j) * 32 + lane]);
            }

            // ---- pointwise (redundant per CTA) ----
            {
                const int d = tid;
                const float gw = (l == 0) ? gw0 : gw1;
                const float gb = (l == 0) ? gb0 : gb1;
                const float4* st4 = (const float4*)(&d_gstat[l * NCTA + b * 8]);
                float m_[4], r_[4];
#pragma unroll
                for (int q = 0; q < 4; q++) {
                    float4 sv = __ldcg(st4 + q);
                    float s  = sv.x + sv.z;
                    float ss = sv.y + sv.w;
                    float m  = s * (1.f / 512.f);
                    float v  = fmaf(-m, m, ss * (1.f / 512.f));
                    m_[q] = m;
                    r_[q] = rsqrtf(v + LN_EPS);
                }
                float xi = __ldcg(gates + d);
                float xf = __ldcg(gates + 512 + d);
                float xg = __ldcg(gates + 1024 + d);
                float xo = __ldcg(gates + 1536 + d);
                float iv = sigmoidf_(fmaf((xi - m_[0]) * r_[0], gw, gb));
                float fv = sigmoidf_(fmaf((xf - m_[1]) * r_[1], gw, gb));
                float gv = tanhf_(   fmaf((xg - m_[2]) * r_[2], gw, gb));
                float ov = sigmoidf_(fmaf((xo - m_[3]) * r_[3], gw, gb));
                float cn = fmaf(fv, creg, iv * gv);
                creg = cn;

                float a = cn, c2 = cn * cn;
#pragma unroll
                for (int o = 16; o > 0; o >>= 1) {
                    a  += __shfl_down_sync(0xffffffffu, a, o);
                    c2 += __shfl_down_sync(0xffffffffu, c2, o);
                }
                if (lane == 0) s_red[wid] = make_float2(a, c2);
                __syncthreads();
                if (tid == 0) {
                    float sa = 0.f, sb = 0.f;
#pragma unroll
                    for (int i = 0; i < NWARP; i++) { sa += s_red[i].x; sb += s_red[i].y; }
                    float m = sa * (1.f / 512.f);
                    float v = fmaf(-m, m, sb * (1.f / 512.f));
                    s_c[0] = m;
                    s_c[1] = rsqrtf(v + LN_EPS);
                }
                __syncthreads();
                float cm = s_c[0], cr = s_c[1];
                float hv = ov * tanhf_(fmaf((cn - cm) * cr, gw, gb));
                s_h2[d] = __float2half_rn(hv);
                if (l == 1 && k == 0)
                    out[((size_t)b * SEQ + t) * DIM + d] = hv;
                __syncthreads();   // s_h2 ready before next matvec
            }
        }
    }
}

extern "C" void kernel_launch(void* const* d_in, const int* in_sizes, int n_in,
                              void* d_out, int out_size) {
    const float* x    = (const float*)d_in[0];
    const float* wih0 = (const float*)d_in[1];
    const float* whh0 = (const float*)d_in[2];
    const float* bih0 = (const float*)d_in[3];
    const float* bhh0 = (const float*)d_in[4];
    const float* wih1 = (const float*)d_in[5];
    const float* whh1 = (const float*)d_in[6];
    const float* bih1 = (const float*)d_in[7];
    const float* bhh1 = (const float*)d_in[8];
    const float* ln_w = (const float*)d_in[9];
    const float* ln_b = (const float*)d_in[10];
    float* out = (float*)d_out;

    cudaFuncSetAttribute(lstm_kernel, cudaFuncAttributeMaxDynamicSharedMemorySize,
                         SMEM_TOTAL);
    cudaFuncSetAttribute(gemm_pre0_h, cudaFuncAttributeMaxDynamicSharedMemorySize,
                         4 * KT * 32 * 16);

    prep_kernel<<<1024, 256>>>(x, wih0, whh0, wih1, whh1, bih1, bhh1);
    gemm_pre0_h<<<dim3(32, 16), 256, 4 * KT * 32 * 16>>>(bih0, bhh0);
    lstm_kernel<<<NCTA, TPB, SMEM_TOTAL>>>(ln_w, ln_b, out);
}

// round 12
// speedup vs baseline: 1.0773x; 1.0020x over previous
#include <cuda_runtime.h>
#include <cuda_fp16.h>
#include <cstdint>

#define BATCH 16
#define SEQ   256
#define DIM   512
#define G4    2048
#define LN_EPS 1e-5f

#define GROUPS 8                  // CTAs per batch
#define NCTA  (BATCH*GROUPS)     // 128
#define TPB   512
#define NWARP 16
#define KT    32                 // 16-wide k-tiles per row-block (512/16)
#define CKT   13                 // SMEM-cached k-tiles per layer per warp
#define PF    6                  // register-prefetched streamed tiles
#define WARP_CACHE_U4 (2*CKT*32)               // 832 uint4/warp
#define SMEM_W_BYTES (NWARP*WARP_CACHE_U4*16)  // 212992
#define OFF_H2  SMEM_W_BYTES                   // fp16 h buffer (1 KB)
#define OFF_RED (OFF_H2 + 1024)
#define OFF_C   (OFF_RED + NWARP*8)
#define SMEM_TOTAL (OFF_C + 16)

#define NFRAG ((size_t)BATCH*128*KT*32)        // uint4 fragment chunks (32 MB each)
#define NXF   ((size_t)BATCH*32*KT*32)         // x B-fragments (uint2): 4 MB

// ---------------- static device scratch ----------------
__device__ uint4   d_w0f[NFRAG];              // whh0, A-fragment-major fp16
__device__ uint4   d_w1f[NFRAG];              // wih1+whh1, A-fragment-major fp16
__device__ uint4   d_wxf[NFRAG];              // wih0, A-fragment-major fp16
__device__ uint2   d_xf [NXF];                // x, B-fragment-major fp16
__device__ float   d_pre0[(size_t)BATCH*SEQ*G4];
__device__ float   d_bias1[BATCH*G4];
__device__ float   d_gates[2*BATCH*G4];       // double-buffered by layer
__device__ float2  d_gstat[2*NCTA];
__device__ unsigned d_bar[BATCH*32];

// ---------------- helpers ----------------
__device__ __forceinline__ unsigned f2h2(float a, float b) {
    __half2 h = __floats2half2_rn(a, b);
    return *reinterpret_cast<unsigned*>(&h);
}
__device__ __forceinline__ float sigmoidf_(float x) {
    return __fdividef(1.f, 1.f + __expf(-x));
}
__device__ __forceinline__ float tanhf_(float x) {
    x = fminf(fmaxf(x, -12.f), 12.f);
    float t = __expf(2.f * x);
    return __fdividef(t - 1.f, t + 1.f);
}

#define MMA16816(d, v, hb)                                                        \
    asm volatile("mma.sync.aligned.m16n8k16.row.col.f32.f16.f16.f32 "             \
                 "{%0,%1,%2,%3},{%4,%5,%6,%7},{%8,%9},{%0,%1,%2,%3};"             \
                 : "+f"(d[0]), "+f"(d[1]), "+f"(d[2]), "+f"(d[3])                 \
                 : "r"(v.x), "r"(v.z), "r"(v.y), "r"(v.w), "r"(hb.x), "r"(hb.y))

// ---------------- prep: build A/B-fragment fp16 tensors ----------------
__global__ void prep_kernel(const float* __restrict__ x,
                            const float* __restrict__ wih0,
                            const float* __restrict__ whh0,
                            const float* __restrict__ wih1,
                            const float* __restrict__ whh1,
                            const float* __restrict__ bih1,
                            const float* __restrict__ bhh1)
{
    size_t idx0 = (size_t)blockIdx.x * blockDim.x + threadIdx.x;
    size_t stride = (size_t)gridDim.x * blockDim.x;
    for (size_t i = idx0; i < NFRAG; i += stride) {
        unsigned lane = (unsigned)i & 31u;
        unsigned kt   = ((unsigned)(i >> 5)) & 31u;
        unsigned blk  = ((unsigned)(i >> 10)) & 127u;
        unsigned b    = (unsigned)(i >> 17);
        unsigned gid  = lane >> 2, tig = lane & 3;
        size_t s0 = ((size_t)b * G4 + blk * 16 + gid) * DIM + kt * 16 + tig * 4;
        size_t s1 = s0 + 8 * DIM;
        {
            float4 A0 = *(const float4*)(whh0 + s0);
            float4 A1 = *(const float4*)(whh0 + s1);
            uint4 o;
            o.x = f2h2(A0.x, A0.y); o.y = f2h2(A0.z, A0.w);
            o.z = f2h2(A1.x, A1.y); o.w = f2h2(A1.z, A1.w);
            d_w0f[i] = o;
        }
        {
            float4 A0 = *(const float4*)(wih0 + s0);
            float4 A1 = *(const float4*)(wih0 + s1);
            uint4 o;
            o.x = f2h2(A0.x, A0.y); o.y = f2h2(A0.z, A0.w);
            o.z = f2h2(A1.x, A1.y); o.w = f2h2(A1.z, A1.w);
            d_wxf[i] = o;
        }
        {
            float4 U0 = *(const float4*)(wih1 + s0);
            float4 V0 = *(const float4*)(whh1 + s0);
            float4 U1 = *(const float4*)(wih1 + s1);
            float4 V1 = *(const float4*)(whh1 + s1);
            uint4 o;
            o.x = f2h2(U0.x + V0.x, U0.y + V0.y); o.y = f2h2(U0.z + V0.z, U0.w + V0.w);
            o.z = f2h2(U1.x + V1.x, U1.y + V1.y); o.w = f2h2(U1.z + V1.z, U1.w + V1.w);
            d_w1f[i] = o;
        }
    }
    // x B-fragments: d_xf[((b*32+tg)*KT+kt)*32+lane] = x[b][tg*8+gid][kt*16+tig*4 ..+3]
    for (size_t i = idx0; i < NXF; i += stride) {
        unsigned lane = (unsigned)i & 31u;
        unsigned kt   = ((unsigned)(i >> 5)) & 31u;
        unsigned tg   = ((unsigned)(i >> 10)) & 31u;
        unsigned b    = (unsigned)(i >> 15);
        unsigned gid  = lane >> 2, tig = lane & 3;
        float4 xv = *(const float4*)(x + ((size_t)(b * SEQ + tg * 8 + gid) * DIM
                                          + kt * 16 + tig * 4));
        d_xf[i] = make_uint2(f2h2(xv.x, xv.y), f2h2(xv.z, xv.w));
    }
    if (idx0 < BATCH * G4) d_bias1[idx0] = bih1[idx0] + bhh1[idx0];
    if (idx0 < BATCH * 32) d_bar[idx0] = 0u;
}

// ---- HMMA GEMM: d_pre0[b][t][j] = wih0[b]@x[b,t] + bih0 + bhh0 ----
__global__ void __launch_bounds__(256) gemm_pre0_h(const float* __restrict__ bih0,
                                                   const float* __restrict__ bhh0)
{
    extern __shared__ __align__(16) unsigned char gsm[];
    uint4* s_a = (uint4*)gsm;                      // 4 * KT * 32 uint4 = 64 KB

    const int b  = blockIdx.y;
    const int rg = blockIdx.x;                     // 0..31 -> rowblocks rg*4..rg*4+3
    const int tid = threadIdx.x;
    const int wid = tid >> 5;
    const int lane = tid & 31;
    const int gid = lane >> 2;
    const int tig = lane & 3;

    const uint4* Asrc = d_wxf + ((size_t)b * 128 + rg * 4) * (KT * 32);
    for (int i = tid; i < 4 * KT * 32; i += 256) s_a[i] = Asrc[i];
    __syncthreads();

    const int rb = wid >> 1;
    const int row0g = (rg * 4 + rb) * 16;
    const uint4* As = s_a + rb * (KT * 32);
    const float bias0 = __ldg(bih0 + b * G4 + row0g + gid)
                      + __ldg(bhh0 + b * G4 + row0g + gid);
    const float bias1 = __ldg(bih0 + b * G4 + row0g + gid + 8)
                      + __ldg(bhh0 + b * G4 + row0g + gid + 8);

    const int tg0 = (wid & 1) * 16;
    for (int tg = tg0; tg < tg0 + 16; tg++) {
        const uint2* xf = d_xf + ((size_t)(b * 32 + tg) * KT) * 32;
        float d0[4] = {0.f, 0.f, 0.f, 0.f};
        float d1[4] = {0.f, 0.f, 0.f, 0.f};
#pragma unroll
        for (int kt = 0; kt < KT; kt++) {
            uint4 v  = As[kt * 32 + lane];
            uint2 hb = __ldg(&xf[kt * 32 + lane]);
            if (kt & 1) { MMA16816(d1, v, hb); }
            else        { MMA16816(d0, v, hb); }
        }
        const int t = tg * 8;
        float* base = d_pre0 + ((size_t)b * SEQ + t) * G4;
        base[(2 * tig)     * G4 + row0g + gid]     = d0[0] + d1[0] + bias0;
        base[(2 * tig + 1) * G4 + row0g + gid]     = d0[1] + d1[1] + bias0;
        base[(2 * tig)     * G4 + row0g + gid + 8] = d0[2] + d1[2] + bias1;
        base[(2 * tig + 1) * G4 + row0g + gid + 8] = d0[3] + d1[3] + bias1;
    }
}

// ---------------- persistent LSTM kernel ----------------
__device__ __forceinline__ void group_barrier(unsigned* bar, unsigned* epoch, int tid) {
    __syncthreads();
    *epoch += GROUPS;
    unsigned target = *epoch;
    if (tid == 0) {
        asm volatile("red.release.gpu.global.add.u32 [%0],%1;"
                     :: "l"(bar), "r"(1u) : "memory");
        unsigned v;
        do {
            asm volatile("ld.acquire.gpu.global.u32 %0,[%1];"
                         : "=r"(v) : "l"(bar) : "memory");
        } while (v < target);
    }
    __syncthreads();
}

__global__ void __launch_bounds__(TPB, 1)
lstm_kernel(const float* __restrict__ lnw, const float* __restrict__ lnb,
            float* __restrict__ out)
{
    extern __shared__ __align__(16) unsigned char smem[];
    uint4*  s_w   = (uint4*)smem;
    __half* s_h2  = (__half*)(smem + OFF_H2);
    float2* s_red = (float2*)(smem + OFF_RED);
    float*  s_c   = (float*)(smem + OFF_C);

    const int cta = blockIdx.x;
    const int b   = cta >> 3;
    const int k   = cta & 7;
    const int tid = threadIdx.x;
    const int wid = tid >> 5;
    const int lane = tid & 31;
    const int gid = lane >> 2;
    const int tig = lane & 3;

    unsigned* bar = &d_bar[b * 32];
    unsigned epoch = 0;
    const int blk  = k * 16 + wid;        // global 16-row block id within batch
    const int row0 = blk * 16;

    const uint4* Wg0 = d_w0f + ((size_t)b * 128 + blk) * (KT * 32);
    const uint4* Wg1 = d_w1f + ((size_t)b * 128 + blk) * (KT * 32);

    // ---- fill SMEM fragment cache: per warp, tiles 0..CKT-1 of each layer ----
    for (int i = tid; i < NWARP * WARP_CACHE_U4; i += TPB) {
        int w  = i / WARP_CACHE_U4;
        int r  = i % WARP_CACHE_U4;
        int l  = r / (CKT * 32);
        int rr = r % (CKT * 32);           // kt*32 + lane
        const uint4* src = (l ? d_w1f : d_w0f)
                         + ((size_t)b * 128 + k * 16 + w) * (KT * 32) + rr;
        s_w[i] = *src;
    }

    const float gw0 = __ldg(lnw + tid),       gb0 = __ldg(lnb + tid);
    const float gw1 = __ldg(lnw + DIM + tid), gb1 = __ldg(lnb + DIM + tid);

    float creg = 0.f;
    ((unsigned short*)s_h2)[tid] = 0;      // h = 0 (fp16)

    // initial prefetch for (t=0, l=0)
    uint4 pf[PF];
#pragma unroll
    for (int j = 0; j < PF; j++) pf[j] = __ldcg(&Wg0[(CKT + j) * 32 + lane]);

    __syncthreads();

    for (int t = 0; t < SEQ; t++) {
#pragma unroll
        for (int l = 0; l < 2; l++) {
            const float* add = (l == 0) ? (d_pre0 + ((size_t)b * SEQ + t) * G4)
                                        : (d_bias1 + (size_t)b * G4);
            float* gates = d_gates + (size_t)l * BATCH * G4 + (size_t)b * G4;
            const uint4* Wg = l ? Wg1 : Wg0;
            const uint4* Ws = s_w + wid * WARP_CACHE_U4 + l * (CKT * 32);
            const char* hbp = (const char*)s_h2 + tig * 8;

            float da[4] = {0.f, 0.f, 0.f, 0.f};
            float db[4] = {0.f, 0.f, 0.f, 0.f};
#pragma unroll
            for (int kt = 0; kt < KT; kt++) {
                uint4 v = (kt < CKT) ? Ws[kt * 32 + lane]
                        : (kt < CKT + PF) ? pf[kt - CKT]
                                          : __ldcg(&Wg[kt * 32 + lane]);
                uint2 hb = *(const uint2*)(hbp + kt * 32);
                if (kt & 1) { MMA16816(db, v, hb); }
                else        { MMA16816(da, v, hb); }
            }
            // every lane's D col is the gate (h replicated over columns)
            float g0 = da[0] + db[0] + __ldg(add + row0 + gid);
            float g1 = da[2] + db[2] + __ldg(add + row0 + 8 + gid);
            if (tig == 0) {
                gates[row0 + gid]     = g0;
                gates[row0 + 8 + gid] = g1;
            }

            // ---- prefetch next layer's streamed tiles NOW: latency hides behind
            //      reduction + barrier spin + stats load (weights are static) ----
#pragma unroll
            for (int j = 0; j < PF; j++)
                pf[j] = __ldcg(&((l ? Wg0 : Wg1)[(CKT + j) * 32 + lane]));

            float s1 = g0 + g1;
            float s2 = fmaf(g0, g0, g1 * g1);
#pragma unroll
            for (int o = 16; o >= 4; o >>= 1) {      // sums lanes 0,4,...,28
                s1 += __shfl_down_sync(0xffffffffu, s1, o);
                s2 += __shfl_down_sync(0xffffffffu, s2, o);
            }
            if (lane == 0) s_red[wid] = make_float2(s1, s2);
            __syncthreads();
            if (tid == 0) {
                float a = 0.f, c = 0.f;
#pragma unroll
                for (int i = 0; i < NWARP; i++) { a += s_red[i].x; c += s_red[i].y; }
                d_gstat[l * NCTA + cta] = make_float2(a, c);
            }
            group_barrier(bar, &epoch, tid);

            // ---- pointwise (redundant per CTA) ----
            {
                const int d = tid;
                const float gw = (l == 0) ? gw0 : gw1;
                const float gb = (l == 0) ? gb0 : gb1;
                const float4* st4 = (const float4*)(&d_gstat[l * NCTA + b * 8]);
                float m_[4], r_[4];
#pragma unroll
                for (int q = 0; q < 4; q++) {
                    float4 sv = __ldcg(st4 + q);
                    float s  = sv.x + sv.z;
                    float ss = sv.y + sv.w;
                    float m  = s * (1.f / 512.f);
                    float v  = fmaf(-m, m, ss * (1.f / 512.f));
                    m_[q] = m;
                    r_[q] = rsqrtf(v + LN_EPS);
                }
                float xi = __ldcg(gates + d);
                float xf = __ldcg(gates + 512 + d);
                float xg = __ldcg(gates + 1024 + d);
                float xo = __ldcg(gates + 1536 + d);
                float iv = sigmoidf_(fmaf((xi - m_[0]) * r_[0], gw, gb));
                float fv = sigmoidf_(fmaf((xf - m_[1]) * r_[1], gw, gb));
                float gv = tanhf_(   fmaf((xg - m_[2]) * r_[2], gw, gb));
                float ov = sigmoidf_(fmaf((xo - m_[3]) * r_[3], gw, gb));
                float cn = fmaf(fv, creg, iv * gv);
                creg = cn;

                float a = cn, c2 = cn * cn;
#pragma unroll
                for (int o = 16; o > 0; o >>= 1) {
                    a  += __shfl_down_sync(0xffffffffu, a, o);
                    c2 += __shfl_down_sync(0xffffffffu, c2, o);
                }
                if (lane == 0) s_red[wid] = make_float2(a, c2);
                __syncthreads();
                if (tid == 0) {
                    float sa = 0.f, sb = 0.f;
#pragma unroll
                    for (int i = 0; i < NWARP; i++) { sa += s_red[i].x; sb += s_red[i].y; }
                    float m = sa * (1.f / 512.f);
                    float v = fmaf(-m, m, sb * (1.f / 512.f));
                    s_c[0] = m;
                    s_c[1] = rsqrtf(v + LN_EPS);
                }
                __syncthreads();
                float cm = s_c[0], cr = s_c[1];
                float hv = ov * tanhf_(fmaf((cn - cm) * cr, gw, gb));
                s_h2[d] = __float2half_rn(hv);
                if (l == 1 && k == 0)
                    out[((size_t)b * SEQ + t) * DIM + d] = hv;
                __syncthreads();   // s_h2 ready before next matvec
            }
        }
    }
}

extern "C" void kernel_launch(void* const* d_in, const int* in_sizes, int n_in,
                              void* d_out, int out_size) {
    const float* x    = (const float*)d_in[0];
    const float* wih0 = (const float*)d_in[1];
    const float* whh0 = (const float*)d_in[2];
    const float* bih0 = (const float*)d_in[3];
    const float* bhh0 = (const float*)d_in[4];
    const float* wih1 = (const float*)d_in[5];
    const float* whh1 = (const float*)d_in[6];
    const float* bih1 = (const float*)d_in[7];
    const float* bhh1 = (const float*)d_in[8];
    const float* ln_w = (const float*)d_in[9];
    const float* ln_b = (const float*)d_in[10];
    float* out = (float*)d_out;

    cudaFuncSetAttribute(lstm_kernel, cudaFuncAttributeMaxDynamicSharedMemorySize,
                         SMEM_TOTAL);
    cudaFuncSetAttribute(gemm_pre0_h, cudaFuncAttributeMaxDynamicSharedMemorySize,
                         4 * KT * 32 * 16);

    prep_kernel<<<1024, 256>>>(x, wih0, whh0, wih1, whh1, bih1, bhh1);
    gemm_pre0_h<<<dim3(32, 16), 256, 4 * KT * 32 * 16>>>(bih0, bhh0);
    lstm_kernel<<<NCTA, TPB, SMEM_TOTAL>>>(ln_w, ln_b, out);
}

// round 13
// speedup vs baseline: 1.0925x; 1.0140x over previous
#include <cuda_runtime.h>
#include <cuda_fp16.h>
#include <cstdint>

#define BATCH 16
#define SEQ   256
#define DIM   512
#define G4    2048
#define LN_EPS 1e-5f

#define GROUPS 8                  // CTAs per batch
#define NCTA  (BATCH*GROUPS)     // 128
#define TPB   512
#define NWARP 16
#define KT    32                 // 16-wide k-tiles per row-block (512/16)
#define CKT   14                 // SMEM-cached k-tiles per layer per warp
#define PF    6                  // register-prefetched streamed tiles
#define WARP_CACHE_U4 (2*CKT*32)               // 896 uint4/warp
#define SMEM_W_BYTES (NWARP*WARP_CACHE_U4*16)  // 229376
#define OFF_H2  SMEM_W_BYTES                   // fp16 h buffer (1 KB)
#define OFF_RED (OFF_H2 + 1024)
#define OFF_C   (OFF_RED + NWARP*8)
#define SMEM_TOTAL (OFF_C + 16)               // ~230.5 KB, 1 CTA/SM

#define NFRAG ((size_t)BATCH*128*KT*32)        // uint4 fragment chunks (32 MB each)
#define NXF   ((size_t)BATCH*32*KT*32)         // x B-fragments (uint2): 4 MB

// ---------------- static device scratch ----------------
__device__ uint4   d_w0f[NFRAG];              // whh0, A-fragment-major fp16
__device__ uint4   d_w1f[NFRAG];              // wih1+whh1, A-fragment-major fp16
__device__ uint4   d_wxf[NFRAG];              // wih0, A-fragment-major fp16
__device__ uint2   d_xf [NXF];                // x, B-fragment-major fp16
__device__ float   d_pre0[(size_t)BATCH*SEQ*G4];
__device__ float   d_bias1[BATCH*G4];
__device__ float   d_gates[2*BATCH*G4];       // double-buffered by layer
__device__ float2  d_gstat[2*NCTA];
__device__ unsigned d_bar[BATCH*32];

// ---------------- helpers ----------------
__device__ __forceinline__ unsigned f2h2(float a, float b) {
    __half2 h = __floats2half2_rn(a, b);
    return *reinterpret_cast<unsigned*>(&h);
}
__device__ __forceinline__ float sigmoidf_(float x) {
    return __fdividef(1.f, 1.f + __expf(-x));
}
__device__ __forceinline__ float tanhf_(float x) {
    x = fminf(fmaxf(x, -12.f), 12.f);
    float t = __expf(2.f * x);
    return __fdividef(t - 1.f, t + 1.f);
}

#define MMA16816(d, v, hb)                                                        \
    asm volatile("mma.sync.aligned.m16n8k16.row.col.f32.f16.f16.f32 "             \
                 "{%0,%1,%2,%3},{%4,%5,%6,%7},{%8,%9},{%0,%1,%2,%3};"             \
                 : "+f"(d[0]), "+f"(d[1]), "+f"(d[2]), "+f"(d[3])                 \
                 : "r"(v.x), "r"(v.z), "r"(v.y), "r"(v.w), "r"(hb.x), "r"(hb.y))

// ---------------- prep: build A/B-fragment fp16 tensors ----------------
__global__ void prep_kernel(const float* __restrict__ x,
                            const float* __restrict__ wih0,
                            const float* __restrict__ whh0,
                            const float* __restrict__ wih1,
                            const float* __restrict__ whh1,
                            const float* __restrict__ bih1,
                            const float* __restrict__ bhh1)
{
    size_t idx0 = (size_t)blockIdx.x * blockDim.x + threadIdx.x;
    size_t stride = (size_t)gridDim.x * blockDim.x;
    for (size_t i = idx0; i < NFRAG; i += stride) {
        unsigned lane = (unsigned)i & 31u;
        unsigned kt   = ((unsigned)(i >> 5)) & 31u;
        unsigned blk  = ((unsigned)(i >> 10)) & 127u;
        unsigned b    = (unsigned)(i >> 17);
        unsigned gid  = lane >> 2, tig = lane & 3;
        size_t s0 = ((size_t)b * G4 + blk * 16 + gid) * DIM + kt * 16 + tig * 4;
        size_t s1 = s0 + 8 * DIM;
        {
            float4 A0 = *(const float4*)(whh0 + s0);
            float4 A1 = *(const float4*)(whh0 + s1);
            uint4 o;
            o.x = f2h2(A0.x, A0.y); o.y = f2h2(A0.z, A0.w);
            o.z = f2h2(A1.x, A1.y); o.w = f2h2(A1.z, A1.w);
            d_w0f[i] = o;
        }
        {
            float4 A0 = *(const float4*)(wih0 + s0);
            float4 A1 = *(const float4*)(wih0 + s1);
            uint4 o;
            o.x = f2h2(A0.x, A0.y); o.y = f2h2(A0.z, A0.w);
            o.z = f2h2(A1.x, A1.y); o.w = f2h2(A1.z, A1.w);
            d_wxf[i] = o;
        }
        {
            float4 U0 = *(const float4*)(wih1 + s0);
            float4 V0 = *(const float4*)(whh1 + s0);
            float4 U1 = *(const float4*)(wih1 + s1);
            float4 V1 = *(const float4*)(whh1 + s1);
            uint4 o;
            o.x = f2h2(U0.x + V0.x, U0.y + V0.y); o.y = f2h2(U0.z + V0.z, U0.w + V0.w);
            o.z = f2h2(U1.x + V1.x, U1.y + V1.y); o.w = f2h2(U1.z + V1.z, U1.w + V1.w);
            d_w1f[i] = o;
        }
    }
    // x B-fragments: d_xf[((b*32+tg)*KT+kt)*32+lane] = x[b][tg*8+gid][kt*16+tig*4 ..+3]
    for (size_t i = idx0; i < NXF; i += stride) {
        unsigned lane = (unsigned)i & 31u;
        unsigned kt   = ((unsigned)(i >> 5)) & 31u;
        unsigned tg   = ((unsigned)(i >> 10)) & 31u;
        unsigned b    = (unsigned)(i >> 15);
        unsigned gid  = lane >> 2, tig = lane & 3;
        float4 xv = *(const float4*)(x + ((size_t)(b * SEQ + tg * 8 + gid) * DIM
                                          + kt * 16 + tig * 4));
        d_xf[i] = make_uint2(f2h2(xv.x, xv.y), f2h2(xv.z, xv.w));
    }
    if (idx0 < BATCH * G4) d_bias1[idx0] = bih1[idx0] + bhh1[idx0];
    if (idx0 < BATCH * 32) d_bar[idx0] = 0u;
}

// ---- HMMA GEMM: d_pre0[b][t][j] = wih0[b]@x[b,t] + bih0 + bhh0 ----
__global__ void __launch_bounds__(256) gemm_pre0_h(const float* __restrict__ bih0,
                                                   const float* __restrict__ bhh0)
{
    extern __shared__ __align__(16) unsigned char gsm[];
    uint4* s_a = (uint4*)gsm;                      // 4 * KT * 32 uint4 = 64 KB

    const int b  = blockIdx.y;
    const int rg = blockIdx.x;                     // 0..31 -> rowblocks rg*4..rg*4+3
    const int tid = threadIdx.x;
    const int wid = tid >> 5;
    const int lane = tid & 31;
    const int gid = lane >> 2;
    const int tig = lane & 3;

    const uint4* Asrc = d_wxf + ((size_t)b * 128 + rg * 4) * (KT * 32);
    for (int i = tid; i < 4 * KT * 32; i += 256) s_a[i] = Asrc[i];
    __syncthreads();

    const int rb = wid >> 1;
    const int row0g = (rg * 4 + rb) * 16;
    const uint4* As = s_a + rb * (KT * 32);
    const float bias0 = __ldg(bih0 + b * G4 + row0g + gid)
                      + __ldg(bhh0 + b * G4 + row0g + gid);
    const float bias1 = __ldg(bih0 + b * G4 + row0g + gid + 8)
                      + __ldg(bhh0 + b * G4 + row0g + gid + 8);

    const int tg0 = (wid & 1) * 16;
    for (int tg = tg0; tg < tg0 + 16; tg++) {
        const uint2* xf = d_xf + ((size_t)(b * 32 + tg) * KT) * 32;
        float d0[4] = {0.f, 0.f, 0.f, 0.f};
        float d1[4] = {0.f, 0.f, 0.f, 0.f};
#pragma unroll
        for (int kt = 0; kt < KT; kt++) {
            uint4 v  = As[kt * 32 + lane];
            uint2 hb = __ldg(&xf[kt * 32 + lane]);
            if (kt & 1) { MMA16816(d1, v, hb); }
            else        { MMA16816(d0, v, hb); }
        }
        const int t = tg * 8;
        float* base = d_pre0 + ((size_t)b * SEQ + t) * G4;
        base[(2 * tig)     * G4 + row0g + gid]     = d0[0] + d1[0] + bias0;
        base[(2 * tig + 1) * G4 + row0g + gid]     = d0[1] + d1[1] + bias0;
        base[(2 * tig)     * G4 + row0g + gid + 8] = d0[2] + d1[2] + bias1;
        base[(2 * tig + 1) * G4 + row0g + gid + 8] = d0[3] + d1[3] + bias1;
    }
}

// ---------------- persistent LSTM kernel ----------------
__device__ __forceinline__ void group_barrier(unsigned* bar, unsigned* epoch, int tid) {
    __syncthreads();
    *epoch += GROUPS;
    unsigned target = *epoch;
    if (tid == 0) {
        asm volatile("red.release.gpu.global.add.u32 [%0],%1;"
                     :: "l"(bar), "r"(1u) : "memory");
        unsigned v;
        do {
            asm volatile("ld.acquire.gpu.global.u32 %0,[%1];"
                         : "=r"(v) : "l"(bar) : "memory");
        } while (v < target);
    }
    __syncthreads();
}

__global__ void __launch_bounds__(TPB, 1)
lstm_kernel(const float* __restrict__ lnw, const float* __restrict__ lnb,
            float* __restrict__ out)
{
    extern __shared__ __align__(16) unsigned char smem[];
    uint4*  s_w   = (uint4*)smem;
    __half* s_h2  = (__half*)(smem + OFF_H2);
    float2* s_red = (float2*)(smem + OFF_RED);
    float*  s_c   = (float*)(smem + OFF_C);

    const int cta = blockIdx.x;
    const int b   = cta >> 3;
    const int k   = cta & 7;
    const int tid = threadIdx.x;
    const int wid = tid >> 5;
    const int lane = tid & 31;
    const int gid = lane >> 2;
    const int tig = lane & 3;

    unsigned* bar = &d_bar[b * 32];
    unsigned epoch = 0;
    const int blk  = k * 16 + wid;        // global 16-row block id within batch
    const int row0 = blk * 16;

    const uint4* Wg0 = d_w0f + ((size_t)b * 128 + blk) * (KT * 32);
    const uint4* Wg1 = d_w1f + ((size_t)b * 128 + blk) * (KT * 32);

    // ---- fill SMEM fragment cache: per warp, tiles 0..CKT-1 of each layer ----
    for (int i = tid; i < NWARP * WARP_CACHE_U4; i += TPB) {
        int w  = i / WARP_CACHE_U4;
        int r  = i % WARP_CACHE_U4;
        int l  = r / (CKT * 32);
        int rr = r % (CKT * 32);           // kt*32 + lane
        const uint4* src = (l ? d_w1f : d_w0f)
                         + ((size_t)b * 128 + k * 16 + w) * (KT * 32) + rr;
        s_w[i] = *src;
    }

    const float gw0 = __ldg(lnw + tid),       gb0 = __ldg(lnb + tid);
    const float gw1 = __ldg(lnw + DIM + tid), gb1 = __ldg(lnb + DIM + tid);

    float creg = 0.f;
    ((unsigned short*)s_h2)[tid] = 0;      // h = 0 (fp16)

    // initial prefetch for (t=0, l=0)
    uint4 pf[PF];
#pragma unroll
    for (int j = 0; j < PF; j++) pf[j] = __ldcg(&Wg0[(CKT + j) * 32 + lane]);

    __syncthreads();

    for (int t = 0; t < SEQ; t++) {
#pragma unroll
        for (int l = 0; l < 2; l++) {
            const float* add = (l == 0) ? (d_pre0 + ((size_t)b * SEQ + t) * G4)
                                        : (d_bias1 + (size_t)b * G4);
            float* gates = d_gates + (size_t)l * BATCH * G4 + (size_t)b * G4;
            const uint4* Wg = l ? Wg1 : Wg0;
            const uint4* Ws = s_w + wid * WARP_CACHE_U4 + l * (CKT * 32);
            const char* hbp = (const char*)s_h2 + tig * 8;

            float da[4] = {0.f, 0.f, 0.f, 0.f};
            float db[4] = {0.f, 0.f, 0.f, 0.f};
#pragma unroll
            for (int kt = 0; kt < KT; kt++) {
                uint4 v = (kt < CKT) ? Ws[kt * 32 + lane]
                        : (kt < CKT + PF) ? pf[kt - CKT]
                                          : __ldcg(&Wg[kt * 32 + lane]);
                uint2 hb = *(const uint2*)(hbp + kt * 32);
                if (kt & 1) { MMA16816(db, v, hb); }
                else        { MMA16816(da, v, hb); }
            }
            // every lane's D col is the gate (h replicated over columns)
            float g0 = da[0] + db[0] + __ldg(add + row0 + gid);
            float g1 = da[2] + db[2] + __ldg(add + row0 + 8 + gid);
            if (tig == 0) {
                gates[row0 + gid]     = g0;
                gates[row0 + 8 + gid] = g1;
            }

            // ---- prefetch next layer's streamed tiles NOW: latency hides behind
            //      reduction + barrier spin + stats load (weights are static) ----
#pragma unroll
            for (int j = 0; j < PF; j++)
                pf[j] = __ldcg(&((l ? Wg0 : Wg1)[(CKT + j) * 32 + lane]));

            float s1 = g0 + g1;
            float s2 = fmaf(g0, g0, g1 * g1);
#pragma unroll
            for (int o = 16; o >= 4; o >>= 1) {      // sums lanes 0,4,...,28
                s1 += __shfl_down_sync(0xffffffffu, s1, o);
                s2 += __shfl_down_sync(0xffffffffu, s2, o);
            }
            if (lane == 0) s_red[wid] = make_float2(s1, s2);
            __syncthreads();
            if (tid == 0) {
                float a = 0.f, c = 0.f;
#pragma unroll
                for (int i = 0; i < NWARP; i++) { a += s_red[i].x; c += s_red[i].y; }
                d_gstat[l * NCTA + cta] = make_float2(a, c);
            }
            group_barrier(bar, &epoch, tid);

            // ---- pointwise (redundant per CTA) ----
            {
                const int d = tid;
                const float gw = (l == 0) ? gw0 : gw1;
                const float gb = (l == 0) ? gb0 : gb1;
                const float4* st4 = (const float4*)(&d_gstat[l * NCTA + b * 8]);
                float m_[4], r_[4];
#pragma unroll
                for (int q = 0; q < 4; q++) {
                    float4 sv = __ldcg(st4 + q);
                    float s  = sv.x + sv.z;
                    float ss = sv.y + sv.w;
                    float m  = s * (1.f / 512.f);
                    float v  = fmaf(-m, m, ss * (1.f / 512.f));
                    m_[q] = m;
                    r_[q] = rsqrtf(v + LN_EPS);
                }
                float xi = __ldcg(gates + d);
                float xf = __ldcg(gates + 512 + d);
                float xg = __ldcg(gates + 1024 + d);
                float xo = __ldcg(gates + 1536 + d);
                float iv = sigmoidf_(fmaf((xi - m_[0]) * r_[0], gw, gb));
                float fv = sigmoidf_(fmaf((xf - m_[1]) * r_[1], gw, gb));
                float gv = tanhf_(   fmaf((xg - m_[2]) * r_[2], gw, gb));
                float ov = sigmoidf_(fmaf((xo - m_[3]) * r_[3], gw, gb));
                float cn = fmaf(fv, creg, iv * gv);
                creg = cn;

                float a = cn, c2 = cn * cn;
#pragma unroll
                for (int o = 16; o > 0; o >>= 1) {
                    a  += __shfl_down_sync(0xffffffffu, a, o);
                    c2 += __shfl_down_sync(0xffffffffu, c2, o);
                }
                if (lane == 0) s_red[wid] = make_float2(a, c2);
                __syncthreads();
                if (tid == 0) {
                    float sa = 0.f, sb = 0.f;
#pragma unroll
                    for (int i = 0; i < NWARP; i++) { sa += s_red[i].x; sb += s_red[i].y; }
                    float m = sa * (1.f / 512.f);
                    float v = fmaf(-m, m, sb * (1.f / 512.f));
                    s_c[0] = m;
                    s_c[1] = rsqrtf(v + LN_EPS);
                }
                __syncthreads();
                float cm = s_c[0], cr = s_c[1];
                float hv = ov * tanhf_(fmaf((cn - cm) * cr, gw, gb));
                s_h2[d] = __float2half_rn(hv);
                if (l == 1 && k == 0)
                    out[((size_t)b * SEQ + t) * DIM + d] = hv;
                __syncthreads();   // s_h2 ready before next matvec
            }
        }
    }
}

extern "C" void kernel_launch(void* const* d_in, const int* in_sizes, int n_in,
                              void* d_out, int out_size) {
    const float* x    = (const float*)d_in[0];
    const float* wih0 = (const float*)d_in[1];
    const float* whh0 = (const float*)d_in[2];
    const float* bih0 = (const float*)d_in[3];
    const float* bhh0 = (const float*)d_in[4];
    const float* wih1 = (const float*)d_in[5];
    const float* whh1 = (const float*)d_in[6];
    const float* bih1 = (const float*)d_in[7];
    const float* bhh1 = (const float*)d_in[8];
    const float* ln_w = (const float*)d_in[9];
    const float* ln_b = (const float*)d_in[10];
    float* out = (float*)d_out;

    cudaFuncSetAttribute(lstm_kernel, cudaFuncAttributeMaxDynamicSharedMemorySize,
                         SMEM_TOTAL);
    cudaFuncSetAttribute(gemm_pre0_h, cudaFuncAttributeMaxDynamicSharedMemorySize,
                         4 * KT * 32 * 16);

    prep_kernel<<<1024, 256>>>(x, wih0, whh0, wih1, whh1, bih1, bhh1);
    gemm_pre0_h<<<dim3(32, 16), 256, 4 * KT * 32 * 16>>>(bih0, bhh0);
    lstm_kernel<<<NCTA, TPB, SMEM_TOTAL>>>(ln_w, ln_b, out);
}